// round 13
// baseline (speedup 1.0000x reference)
#include <cuda_runtime.h>
#include <cuda_bf16.h>
#include <cuda_fp16.h>
#include <cstdint>
#include <math.h>

// Problem constants
#define BATCH 2
#define T_SEQ 2048
#define HID   2048
#define NHEAD 16
#define HDIM  128
#define MROWS (BATCH * T_SEQ)   // 4096
#define KDIM  2048
#define NELEM (BATCH * NHEAD * T_SEQ * HDIM)   // 8M

// ---------------------------------------------------------------------------
// Scratch (device globals; allocation-free kernel_launch)
// ---------------------------------------------------------------------------
__device__ __half g_xh[MROWS * KDIM];           // x fp16; later reused as ao fp16
__device__ __half g_wh[4 * HID * KDIM];         // Wq,Wk,Wv,Wo hi (fp16)
__device__ __half g_wl[4 * HID * KDIM];         // residual lo (fp16)
__device__ __half g_qh16[NELEM];                // [b,h][t][d], pre-scaled+RoPE, single fp16
__device__ __half g_kh16[NELEM];                // [b,h][t][d], RoPE, fp16 hi
__device__ __half g_kl16[NELEM];                // fp16 lo
__device__ __half g_vth16[NELEM];               // [b,h][d][t] transposed, fp16 hi
__device__ __half g_vtl16[NELEM];               // fp16 lo

// ---------------------------------------------------------------------------
// PTX helpers (baseline PTX only)
// ---------------------------------------------------------------------------
__device__ __forceinline__ uint32_t smem_u32(const void* p) {
    uint32_t a;
    asm("{ .reg .u64 t; cvta.to.shared.u64 t, %1; cvt.u32.u64 %0, t; }" : "=r"(a) : "l"(p));
    return a;
}
#define LDM4(r, addr) \
    asm volatile("ldmatrix.sync.aligned.m8n8.x4.shared.b16 {%0,%1,%2,%3}, [%4];" \
        : "=r"((r)[0]), "=r"((r)[1]), "=r"((r)[2]), "=r"((r)[3]) : "r"(addr))
#define MMA_F16(d, a, b0, b1) \
    asm volatile("mma.sync.aligned.m16n8k16.row.col.f32.f16.f16.f32 " \
        "{%0,%1,%2,%3}, {%4,%5,%6,%7}, {%8,%9}, {%0,%1,%2,%3};" \
        : "+f"((d)[0]), "+f"((d)[1]), "+f"((d)[2]), "+f"((d)[3]) \
        : "r"((a)[0]), "r"((a)[1]), "r"((a)[2]), "r"((a)[3]), "r"(b0), "r"(b1))
// fp16-accumulate variant: D,C are 2 regs of half2 (testing half-rate-f32acc hypothesis)
#define MMA_F16ACC(d, a, b0, b1) \
    asm volatile("mma.sync.aligned.m16n8k16.row.col.f16.f16.f16.f16 " \
        "{%0,%1}, {%2,%3,%4,%5}, {%6,%7}, {%0,%1};" \
        : "+r"((d)[0]), "+r"((d)[1]) \
        : "r"((a)[0]), "r"((a)[1]), "r"((a)[2]), "r"((a)[3]), "r"(b0), "r"(b1))
#define CP16(s, g) \
    asm volatile("cp.async.cg.shared.global [%0], [%1], 16;" \
        :: "r"(s), "l"(__cvta_generic_to_global(g)) : "memory")
#define CP_COMMIT() asm volatile("cp.async.commit_group;" ::: "memory")
#define CP_WAIT1()  asm volatile("cp.async.wait_group 1;" ::: "memory")
#define CP_WAIT0()  asm volatile("cp.async.wait_group 0;" ::: "memory")

__device__ __forceinline__ void split_store2h(__half* dh, __half* dl, float a, float b) {
    __half ha = __float2half(a), hb = __float2half(b);
    *(__half2*)dh = __halves2half2(ha, hb);
    *(__half2*)dl = __floats2half2_rn(a - __half2float(ha), b - __half2float(hb));
}

// ---------------------------------------------------------------------------
// fp32 -> fp16 conversion kernels
// ---------------------------------------------------------------------------
struct alignas(8) h2x2 { __half2 a, b; };

__global__ void cvt_h_kernel(const float* __restrict__ src,
                             __half* __restrict__ hi, int n4)
{
    int i = blockIdx.x * blockDim.x + threadIdx.x;
    if (i >= n4) return;
    float4 v = ((const float4*)src)[i];
    h2x2 hv;
    hv.a = __floats2half2_rn(v.x, v.y);
    hv.b = __floats2half2_rn(v.z, v.w);
    ((h2x2*)hi)[i] = hv;
}

// fused hi/lo split for all 4 weight matrices (grid.y = z)
__global__ void split_h4_kernel(const float* __restrict__ W0, const float* __restrict__ W1,
                                const float* __restrict__ W2, const float* __restrict__ W3,
                                __half* __restrict__ hi, __half* __restrict__ lo, int n4)
{
    int z = blockIdx.y;
    const float* src = (z == 0) ? W0 : (z == 1) ? W1 : (z == 2) ? W2 : W3;
    int i = blockIdx.x * blockDim.x + threadIdx.x;
    if (i >= n4) return;
    size_t o = (size_t)z * n4 + i;
    float4 v = ((const float4*)src)[i];
    __half h0 = __float2half(v.x), h1 = __float2half(v.y);
    __half h2 = __float2half(v.z), h3 = __float2half(v.w);
    h2x2 hv, lv;
    hv.a = __half2(h0, h1); hv.b = __half2(h2, h3);
    lv.a = __floats2half2_rn(v.x - __half2float(h0), v.y - __half2float(h1));
    lv.b = __floats2half2_rn(v.z - __half2float(h2), v.w - __half2float(h3));
    ((h2x2*)hi)[o] = hv;
    ((h2x2*)lo)[o] = lv;
}

// ---------------------------------------------------------------------------
// mma.sync fp16 GEMM tile: C[128,128] = A[128,K] * (Bhi+Blo)[128,K]^T.
// Main product fp32-acc; correction product fp16-acc (merged at end).
// 8 warps = 2(M) x 4(N); warp tile 64x32; BK=32; 3-stage cp.async ring.
// ---------------------------------------------------------------------------
#define TILE_B    10240           // 128 * 40 * 2
#define STAGE_B   (3 * TILE_B)    // 30720
#define GEMM_SMEM (3 * STAGE_B)   // 92160

__device__ __forceinline__ void mma_gemm_tile(
    const __half* __restrict__ Ah,
    const __half* __restrict__ Bh, const __half* __restrict__ Bl,
    uint32_t sbase, float acc[4][4][4])
{
    int tid = threadIdx.x, lane = tid & 31, w = tid >> 5;
    int wm = w & 1, wn = w >> 1;
    uint32_t r8 = lane & 7, mi = lane >> 3;
    uint32_t a_off = ((wm * 64 + ((mi & 1) << 3) + r8) * 40 + ((mi >> 1) << 3)) * 2;
    uint32_t b_off = ((wn * 32 + ((mi >> 1) << 3) + r8) * 40 + ((mi & 1) << 3)) * 2;

    uint32_t acc1[4][4][2];   // fp16-acc correction accumulators
#pragma unroll
    for (int i = 0; i < 4; i++)
#pragma unroll
        for (int j = 0; j < 4; j++) { acc1[i][j][0] = 0u; acc1[i][j][1] = 0u; }

    int e0 = tid, e1 = tid + 256;
    int r0 = e0 >> 2, kq0 = e0 & 3;
    int r1 = e1 >> 2, kq1 = e1 & 3;
    uint32_t so0 = (uint32_t)((r0 * 40 + kq0 * 8) * 2);
    uint32_t so1 = (uint32_t)((r1 * 40 + kq1 * 8) * 2);

    auto issue = [&](int c, int buf) {
        uint32_t sb = sbase + buf * STAGE_B;
        size_t gg0 = (size_t)r0 * KDIM + c * 32 + kq0 * 8;
        size_t gg1 = (size_t)r1 * KDIM + c * 32 + kq1 * 8;
        CP16(sb + 0 * TILE_B + so0, Ah + gg0);
        CP16(sb + 0 * TILE_B + so1, Ah + gg1);
        CP16(sb + 1 * TILE_B + so0, Bh + gg0);
        CP16(sb + 1 * TILE_B + so1, Bh + gg1);
        CP16(sb + 2 * TILE_B + so0, Bl + gg0);
        CP16(sb + 2 * TILE_B + so1, Bl + gg1);
    };

    auto compute = [&](int buf) {
        uint32_t sb = sbase + buf * STAGE_B;
#pragma unroll
        for (int ks = 0; ks < 2; ks++) {
            uint32_t k0b = ks * 32;
            uint32_t bh[8], bl[8];
#pragma unroll
            for (int p = 0; p < 2; p++) {
                LDM4(&bh[p * 4], sb + 1 * TILE_B + b_off + p * 1280 + k0b);
                LDM4(&bl[p * 4], sb + 2 * TILE_B + b_off + p * 1280 + k0b);
            }
#pragma unroll
            for (int ma = 0; ma < 4; ma++) {
                uint32_t ah[4];
                LDM4(ah, sb + 0 * TILE_B + a_off + ma * 1280 + k0b);
#pragma unroll
                for (int na = 0; na < 4; na++) {
                    int bi = (na >> 1) * 4 + (na & 1) * 2;
                    MMA_F16(acc[ma][na], ah, bh[bi], bh[bi + 1]);
                    MMA_F16ACC(acc1[ma][na], ah, bl[bi], bl[bi + 1]);
                }
            }
        }
    };

    const int NCH = KDIM / 32;   // 64
    issue(0, 0); CP_COMMIT();
    issue(1, 1); CP_COMMIT();
    for (int c = 0; c < NCH; c++) {
        if (c == NCH - 1) { CP_WAIT0(); } else { CP_WAIT1(); }
        __syncthreads();
        if (c + 2 < NCH) { issue(c + 2, (c + 2) % 3); CP_COMMIT(); }
        compute(c % 3);
    }

    // merge fp16 correction accumulators into fp32 accumulators
#pragma unroll
    for (int ma = 0; ma < 4; ma++)
#pragma unroll
        for (int na = 0; na < 4; na++) {
            __half2 h0 = *(__half2*)&acc1[ma][na][0];
            __half2 h1 = *(__half2*)&acc1[ma][na][1];
            acc[ma][na][0] += __low2float(h0);
            acc[ma][na][1] += __high2float(h0);
            acc[ma][na][2] += __low2float(h1);
            acc[ma][na][3] += __high2float(h1);
        }
    __syncthreads();   // protect smem reuse by caller epilogue
}

// stage acc -> smem float[128][132]
__device__ __forceinline__ void acc_to_smem(float* Cs, float acc[4][4][4])
{
    int tid = threadIdx.x, lane = tid & 31, w = tid >> 5;
    int wm = w & 1, wn = w >> 1;
    int g = lane >> 2, tg = lane & 3;
#pragma unroll
    for (int ma = 0; ma < 4; ma++)
#pragma unroll
        for (int na = 0; na < 4; na++) {
            int col = wn * 32 + na * 8 + tg * 2;
            int row = wm * 64 + ma * 16 + g;
            *(float2*)&Cs[row * 132 + col]       = make_float2(acc[ma][na][0], acc[ma][na][1]);
            *(float2*)&Cs[(row + 8) * 132 + col] = make_float2(acc[ma][na][2], acc[ma][na][3]);
        }
}

// ---------------------------------------------------------------------------
// QKV projection: GEMM + RoPE(+scale) + fp16 stores in flash layouts.
// grid (16, 32, 3): n-block = head, m-block = 128 tokens, z = Q/K/V.
// ---------------------------------------------------------------------------
__global__ __launch_bounds__(256, 1)
void qkv_mma_kernel(const __half* __restrict__ xh,
                    const __half* __restrict__ wh, const __half* __restrict__ wl,
                    const float* __restrict__ cosb, const float* __restrict__ sinb)
{
    extern __shared__ char smem[];
    uint32_t sbase = smem_u32(smem);
    int tid = threadIdx.x;
    int z = blockIdx.z;
    int n0 = blockIdx.x * 128, m0 = blockIdx.y * 128;
    int h = n0 >> 7;
    int b = m0 >> 11, t0 = m0 & 2047;
    int bh = b * NHEAD + h;

    const __half* Ah = xh + (size_t)m0 * KDIM;
    const __half* Bh = wh + (size_t)z * HID * KDIM + (size_t)n0 * KDIM;
    const __half* Bl = wl + (size_t)z * HID * KDIM + (size_t)n0 * KDIM;

    float acc[4][4][4];
#pragma unroll
    for (int i = 0; i < 4; i++)
#pragma unroll
        for (int j = 0; j < 4; j++)
#pragma unroll
            for (int c = 0; c < 4; c++) acc[i][j][c] = 0.f;

    mma_gemm_tile(Ah, Bh, Bl, sbase, acc);

    float* Cs = (float*)smem;
    acc_to_smem(Cs, acc);
    __syncthreads();

    if (z < 2) {
        // RoPE (+scale for Q); Q single fp16, K split fp16; store [bh][t][d]
        const float qscale = (z == 0) ? 0.08838834764831845f : 1.0f;
        int r = tid >> 1, half = tid & 1;
        int t = t0 + r;
        int d0 = half * 32;
        size_t rowoff = ((size_t)bh * T_SEQ + t0 + r) * HDIM;
#pragma unroll
        for (int j = 0; j < 32; j += 2) {
            int d = d0 + j;
            float a0 = Cs[r * 132 + d],      a1 = Cs[r * 132 + d + 1];
            float b0 = Cs[r * 132 + d + 64], b1 = Cs[r * 132 + d + 65];
            float c00 = cosb[t * HDIM + d],      s00 = sinb[t * HDIM + d];
            float c01 = cosb[t * HDIM + d + 1],  s01 = sinb[t * HDIM + d + 1];
            float c10 = cosb[t * HDIM + 64 + d],     s10 = sinb[t * HDIM + 64 + d];
            float c11 = cosb[t * HDIM + 64 + d + 1], s11 = sinb[t * HDIM + 64 + d + 1];
            float o00 = (a0 * c00 - b0 * s00) * qscale;
            float o01 = (a1 * c01 - b1 * s01) * qscale;
            float o10 = (b0 * c10 + a0 * s10) * qscale;
            float o11 = (b1 * c11 + a1 * s11) * qscale;
            if (z == 0) {
                *(__half2*)&g_qh16[rowoff + d]      = __floats2half2_rn(o00, o01);
                *(__half2*)&g_qh16[rowoff + 64 + d] = __floats2half2_rn(o10, o11);
            } else {
                split_store2h(&g_kh16[rowoff + d],      &g_kl16[rowoff + d],      o00, o01);
                split_store2h(&g_kh16[rowoff + 64 + d], &g_kl16[rowoff + 64 + d], o10, o11);
            }
        }
    } else {
        // V transpose: store [bh][d][t] split fp16
        __half* dh = g_vth16 + (size_t)bh * HDIM * T_SEQ;
        __half* dl = g_vtl16 + (size_t)bh * HDIM * T_SEQ;
#pragma unroll 4
        for (int i = 0; i < 64; i++) {
            int d = (i & 31) * 4 + (tid >> 6);
            int tl = (i >> 5) * 64 + (tid & 63);
            float val = Cs[tl * 132 + d];
            __half hv = __float2half(val);
            __half lv = __float2half(val - __half2float(hv));
            dh[(size_t)d * T_SEQ + t0 + tl] = hv;
            dl[(size_t)d * T_SEQ + t0 + tl] = lv;
        }
    }
}

// ---------------------------------------------------------------------------
// Flash attention on mma.sync, fp16 2-product, causal. Br=128, Bc=64, D=128.
// Main products fp32-acc; correction products fp16-acc, merged per tile.
// K/V double-buffered. Output fp16 into aoh [m][h*128+d].
// ---------------------------------------------------------------------------
#define FS_Q      0               // 40960: 4 chunks [128][40] fp16
#define FS_STAGE  40960           // 2 stages x 81920 (KH,KL,VH,VL)
#define FS_P      204800          // 20480: 2 chunks [128][40] fp16
#define FLASH_SMEM 225280

__global__ __launch_bounds__(256, 1)
void flash_hmma_kernel(const __half* __restrict__ qh, const __half* __restrict__ khi,
                       const __half* __restrict__ klo, const __half* __restrict__ vthi,
                       const __half* __restrict__ vtlo, __half* __restrict__ aoh)
{
    extern __shared__ char smem[];
    uint32_t sbase = smem_u32(smem);
    int tid = threadIdx.x, lane = tid & 31, w = tid >> 5;
    int bh = blockIdx.y;
    int qi = gridDim.x - 1 - blockIdx.x;   // heavy tiles first
    int qrow0 = qi * 128;

    const __half* qh_b = qh   + (size_t)bh * T_SEQ * HDIM;
    const __half* kh_b = khi  + (size_t)bh * T_SEQ * HDIM;
    const __half* kl_b = klo  + (size_t)bh * T_SEQ * HDIM;
    const __half* vh_b = vthi + (size_t)bh * HDIM * T_SEQ;
    const __half* vl_b = vtlo + (size_t)bh * HDIM * T_SEQ;

    // Stage Q (128 x 128 fp16) into 4 chunks [128][40]
#pragma unroll
    for (int i = 0; i < 8; i++) {
        int e = tid + i * 256;
        int row = e >> 4, u = e & 15;
        uint32_t sa = sbase + FS_Q + (u >> 2) * 10240 + (row * 40 + (u & 3) * 8) * 2;
        CP16(sa, qh_b + (size_t)(qrow0 + row) * HDIM + u * 8);
    }
    CP_COMMIT();

    auto load_kv = [&](int j, int st) {
        uint32_t sb = sbase + FS_STAGE + st * 81920;
#pragma unroll
        for (int i = 0; i < 4; i++) {
            int e = tid + i * 256;
            int row = e >> 4, u = e & 15;
            uint32_t sa = sb + (u >> 2) * 5120 + (row * 40 + (u & 3) * 8) * 2;
            size_t go = (size_t)(j * 64 + row) * HDIM + u * 8;
            CP16(sa, kh_b + go);
            CP16(sa + 20480, kl_b + go);
        }
#pragma unroll
        for (int i = 0; i < 4; i++) {
            int e = tid + i * 256;
            int d = e >> 3, u = e & 7;
            uint32_t sa = sb + 40960 + (u >> 2) * 10240 + (d * 40 + (u & 3) * 8) * 2;
            size_t go = (size_t)d * T_SEQ + j * 64 + u * 8;
            CP16(sa, vh_b + go);
            CP16(sa + 20480, vl_b + go);
        }
        CP_COMMIT();
    };

    uint32_t r8 = lane & 7, mi = lane >> 3;
    int tg = lane & 3, g = lane >> 2;
    uint32_t aoff = ((w * 16 + (mi & 1) * 8 + r8) * 40 + (mi >> 1) * 8) * 2;
    uint32_t boff = (((mi >> 1) * 8 + r8) * 40 + (mi & 1) * 8) * 2;

    float oacc[16][4];
#pragma unroll
    for (int i = 0; i < 16; i++)
#pragma unroll
        for (int c = 0; c < 4; c++) oacc[i][c] = 0.f;
    float mrow0 = -1e30f, mrow1 = -1e30f, lrow0 = 0.f, lrow1 = 0.f;

    int row0l = w * 16 + g;
    int gr0 = qrow0 + row0l, gr1 = gr0 + 8;
    int jmax = 2 * qi + 1;

    load_kv(0, 0);

    for (int j = 0; j <= jmax; j++) {
        if (j < jmax) { load_kv(j + 1, (j + 1) & 1); CP_WAIT1(); }
        else          { CP_WAIT0(); }
        __syncthreads();
        uint32_t kb = sbase + FS_STAGE + (j & 1) * 81920;
        uint32_t vb = kb + 40960;

        // S = Q K^T: main fp32-acc, corr fp16-acc
        float sacc[8][4];
        uint32_t sacc1[8][2];
#pragma unroll
        for (int i = 0; i < 8; i++) {
#pragma unroll
            for (int c = 0; c < 4; c++) sacc[i][c] = 0.f;
            sacc1[i][0] = 0u; sacc1[i][1] = 0u;
        }

#pragma unroll
        for (int ks = 0; ks < 8; ks++) {
            uint32_t ko = (ks & 1) * 32;
            uint32_t q4[4];
            LDM4(q4, sbase + FS_Q + (ks >> 1) * 10240 + aoff + ko);
#pragma unroll
            for (int nb = 0; nb < 4; nb++) {
                uint32_t kh4[4], kl4[4];
                LDM4(kh4, kb + (ks >> 1) * 5120 + boff + nb * 1280 + ko);
                LDM4(kl4, kb + 20480 + (ks >> 1) * 5120 + boff + nb * 1280 + ko);
                MMA_F16(sacc[nb * 2],        q4, kh4[0], kh4[1]);
                MMA_F16ACC(sacc1[nb * 2],    q4, kl4[0], kl4[1]);
                MMA_F16(sacc[nb * 2 + 1],    q4, kh4[2], kh4[3]);
                MMA_F16ACC(sacc1[nb * 2 + 1], q4, kl4[2], kl4[3]);
            }
        }
        // merge corr into sacc
#pragma unroll
        for (int na = 0; na < 8; na++) {
            __half2 h0 = *(__half2*)&sacc1[na][0];
            __half2 h1 = *(__half2*)&sacc1[na][1];
            sacc[na][0] += __low2float(h0);
            sacc[na][1] += __high2float(h0);
            sacc[na][2] += __low2float(h1);
            sacc[na][3] += __high2float(h1);
        }

        // causal mask (only the two diagonal tiles need it)
        if (j >= 2 * qi) {
#pragma unroll
            for (int na = 0; na < 8; na++) {
                int gc = j * 64 + na * 8 + tg * 2;
                if (gc     > gr0) sacc[na][0] = -1e30f;
                if (gc + 1 > gr0) sacc[na][1] = -1e30f;
                if (gc     > gr1) sacc[na][2] = -1e30f;
                if (gc + 1 > gr1) sacc[na][3] = -1e30f;
            }
        }

        // online softmax (rows gr0, gr1); reduce over 4-lane tg group
        float m0 = -1e30f, m1 = -1e30f;
#pragma unroll
        for (int na = 0; na < 8; na++) {
            m0 = fmaxf(m0, fmaxf(sacc[na][0], sacc[na][1]));
            m1 = fmaxf(m1, fmaxf(sacc[na][2], sacc[na][3]));
        }
        m0 = fmaxf(m0, __shfl_xor_sync(0xffffffffu, m0, 1));
        m0 = fmaxf(m0, __shfl_xor_sync(0xffffffffu, m0, 2));
        m1 = fmaxf(m1, __shfl_xor_sync(0xffffffffu, m1, 1));
        m1 = fmaxf(m1, __shfl_xor_sync(0xffffffffu, m1, 2));
        float mn0 = fmaxf(mrow0, m0), mn1 = fmaxf(mrow1, m1);
        float cr0 = __expf(mrow0 - mn0), cr1 = __expf(mrow1 - mn1);
        float s0 = 0.f, s1 = 0.f;
#pragma unroll
        for (int na = 0; na < 8; na++) {
            float p00 = __expf(sacc[na][0] - mn0);
            float p01 = __expf(sacc[na][1] - mn0);
            float p10 = __expf(sacc[na][2] - mn1);
            float p11 = __expf(sacc[na][3] - mn1);
            s0 += p00 + p01; s1 += p10 + p11;
            // P single fp16 store (chunked [128][40], warp-private rows)
            char* basep = smem + FS_P + (na >> 2) * 10240;
            uint32_t cw = (na & 3) * 8 + tg * 2;
            *(__half2*)(basep + (row0l * 40 + cw) * 2)       = __floats2half2_rn(p00, p01);
            *(__half2*)(basep + ((row0l + 8) * 40 + cw) * 2) = __floats2half2_rn(p10, p11);
        }
        s0 += __shfl_xor_sync(0xffffffffu, s0, 1);
        s0 += __shfl_xor_sync(0xffffffffu, s0, 2);
        s1 += __shfl_xor_sync(0xffffffffu, s1, 1);
        s1 += __shfl_xor_sync(0xffffffffu, s1, 2);
        lrow0 = lrow0 * cr0 + s0;  lrow1 = lrow1 * cr1 + s1;
        mrow0 = mn0;               mrow1 = mn1;
#pragma unroll
        for (int na = 0; na < 16; na++) {
            oacc[na][0] *= cr0; oacc[na][1] *= cr0;
            oacc[na][2] *= cr1; oacc[na][3] *= cr1;
        }
        __syncwarp();

        // O += P V: main fp32-acc, corr fp16-acc (merged per tile)
        uint32_t oacc1[16][2];
#pragma unroll
        for (int i = 0; i < 16; i++) { oacc1[i][0] = 0u; oacc1[i][1] = 0u; }
#pragma unroll
        for (int kvs = 0; kvs < 4; kvs++) {
            uint32_t ko = (kvs & 1) * 32;
            uint32_t p4[4];
            LDM4(p4, sbase + FS_P + (kvs >> 1) * 10240 + aoff + ko);
#pragma unroll
            for (int nb = 0; nb < 8; nb++) {
                uint32_t vh4[4], vl4[4];
                LDM4(vh4, vb + (kvs >> 1) * 10240 + boff + nb * 1280 + ko);
                LDM4(vl4, vb + 20480 + (kvs >> 1) * 10240 + boff + nb * 1280 + ko);
                MMA_F16(oacc[nb * 2],        p4, vh4[0], vh4[1]);
                MMA_F16ACC(oacc1[nb * 2],    p4, vl4[0], vl4[1]);
                MMA_F16(oacc[nb * 2 + 1],    p4, vh4[2], vh4[3]);
                MMA_F16ACC(oacc1[nb * 2 + 1], p4, vl4[2], vl4[3]);
            }
        }
#pragma unroll
        for (int na = 0; na < 16; na++) {
            __half2 h0 = *(__half2*)&oacc1[na][0];
            __half2 h1 = *(__half2*)&oacc1[na][1];
            oacc[na][0] += __low2float(h0);
            oacc[na][1] += __high2float(h0);
            oacc[na][2] += __low2float(h1);
            oacc[na][3] += __high2float(h1);
        }
        __syncthreads();   // all warps done with this stage before overwrite at j+2
    }

    // epilogue: normalize, convert fp16, store into Wo's A layout [m][h*128+d]
    int bb = bh >> 4, hh = bh & 15;
    float inv0 = 1.f / lrow0, inv1 = 1.f / lrow1;
    size_t m0i = (size_t)(bb * T_SEQ + gr0) * HID + hh * HDIM;
    size_t m1i = (size_t)(bb * T_SEQ + gr1) * HID + hh * HDIM;
#pragma unroll
    for (int na = 0; na < 16; na++) {
        int col = na * 8 + tg * 2;
        *(__half2*)&aoh[m0i + col] = __floats2half2_rn(oacc[na][0] * inv0, oacc[na][1] * inv0);
        *(__half2*)&aoh[m1i + col] = __floats2half2_rn(oacc[na][2] * inv1, oacc[na][3] * inv1);
    }
}

// ---------------------------------------------------------------------------
// Output projection on mma.sync: out[m, n] row-major fp32.
// ---------------------------------------------------------------------------
__global__ __launch_bounds__(256, 1)
void wo_mma_kernel(const __half* __restrict__ ah,
                   const __half* __restrict__ wh, const __half* __restrict__ wl,
                   float* __restrict__ out)
{
    extern __shared__ char smem[];
    uint32_t sbase = smem_u32(smem);
    int tid = threadIdx.x;
    int n0 = blockIdx.x * 128, m0 = blockIdx.y * 128;

    const __half* Ah = ah + (size_t)m0 * KDIM;
    const __half* Bh = wh + (size_t)3 * HID * KDIM + (size_t)n0 * KDIM;
    const __half* Bl = wl + (size_t)3 * HID * KDIM + (size_t)n0 * KDIM;

    float acc[4][4][4];
#pragma unroll
    for (int i = 0; i < 4; i++)
#pragma unroll
        for (int j = 0; j < 4; j++)
#pragma unroll
            for (int c = 0; c < 4; c++) acc[i][j][c] = 0.f;

    mma_gemm_tile(Ah, Bh, Bl, sbase, acc);

    float* Cs = (float*)smem;
    acc_to_smem(Cs, acc);
    __syncthreads();

    int r = tid >> 1, half = tid & 1;
    float* outp = out + (size_t)(m0 + r) * HID + n0 + half * 64;
#pragma unroll
    for (int j = 0; j < 64; j += 4)
        *(float4*)&outp[j] = *(float4*)&Cs[r * 132 + half * 64 + j];
}

// ---------------------------------------------------------------------------
extern "C" void kernel_launch(void* const* d_in, const int* in_sizes, int n_in,
                              void* d_out, int out_size)
{
    const float* x    = (const float*)d_in[0];
    const float* cosb = (const float*)d_in[1];
    const float* sinb = (const float*)d_in[2];
    const float* Wq   = (const float*)d_in[3];
    const float* Wk   = (const float*)d_in[4];
    const float* Wv   = (const float*)d_in[5];
    const float* Wo   = (const float*)d_in[6];
    float* out = (float*)d_out;

    __half *xh, *wh, *wl, *qh, *kh, *kl, *vth, *vtl;
    cudaGetSymbolAddress((void**)&xh,  g_xh);
    cudaGetSymbolAddress((void**)&wh,  g_wh);
    cudaGetSymbolAddress((void**)&wl,  g_wl);
    cudaGetSymbolAddress((void**)&qh,  g_qh16);
    cudaGetSymbolAddress((void**)&kh,  g_kh16);
    cudaGetSymbolAddress((void**)&kl,  g_kl16);
    cudaGetSymbolAddress((void**)&vth, g_vth16);
    cudaGetSymbolAddress((void**)&vtl, g_vtl16);

    // 1) x -> fp16; weights -> fp16 hi/lo split (one fused launch)
    const int XN4 = MROWS * KDIM / 4;
    const int WN4 = HID * KDIM / 4;
    cvt_h_kernel<<<XN4 / 256, 256>>>(x, xh, XN4);
    split_h4_kernel<<<dim3(WN4 / 256, 4), 256>>>(Wq, Wk, Wv, Wo, wh, wl, WN4);

    // 2) QKV projection + RoPE + layout fusion (fp16 flash buffers)
    cudaFuncSetAttribute(qkv_mma_kernel, cudaFuncAttributeMaxDynamicSharedMemorySize, GEMM_SMEM);
    qkv_mma_kernel<<<dim3(HID / 128, MROWS / 128, 3), 256, GEMM_SMEM>>>(
        xh, wh, wl, cosb, sinb);

    // 3) flash attention (fp16 2-product, double-buffered K/V); out -> g_xh
    cudaFuncSetAttribute(flash_hmma_kernel, cudaFuncAttributeMaxDynamicSharedMemorySize, FLASH_SMEM);
    flash_hmma_kernel<<<dim3(T_SEQ / 128, BATCH * NHEAD), 256, FLASH_SMEM>>>(
        qh, kh, kl, vth, vtl, xh);

    // 4) output projection (fp16 2-product)
    cudaFuncSetAttribute(wo_mma_kernel, cudaFuncAttributeMaxDynamicSharedMemorySize, GEMM_SMEM);
    wo_mma_kernel<<<dim3(HID / 128, MROWS / 128), 256, GEMM_SMEM>>>(xh, wh, wl, out);
}

// round 15
// speedup vs baseline: 1.0777x; 1.0777x over previous
#include <cuda_runtime.h>
#include <cuda_bf16.h>
#include <cuda_fp16.h>
#include <cstdint>
#include <math.h>

// Problem constants
#define BATCH 2
#define T_SEQ 2048
#define HID   2048
#define NHEAD 16
#define HDIM  128
#define MROWS (BATCH * T_SEQ)   // 4096
#define KDIM  2048
#define NELEM (BATCH * NHEAD * T_SEQ * HDIM)   // 8M

// ---------------------------------------------------------------------------
// Scratch (device globals; allocation-free kernel_launch)
// ---------------------------------------------------------------------------
__device__ __half g_xh[MROWS * KDIM];           // x fp16; later reused as ao fp16
__device__ __half g_wh[4 * HID * KDIM];         // Wq,Wk,Wv,Wo hi (fp16)
__device__ __half g_wl[4 * HID * KDIM];         // residual lo (fp16)
__device__ __half g_qh16[NELEM];                // [b,h][t][d], pre-scaled+RoPE, single fp16
__device__ __half g_kh16[NELEM];                // [b,h][t][d], RoPE, fp16 hi
__device__ __half g_kl16[NELEM];                // fp16 lo
__device__ __half g_vth16[NELEM];               // [b,h][d][t] transposed, fp16 hi
__device__ __half g_vtl16[NELEM];               // fp16 lo

// ---------------------------------------------------------------------------
// PTX helpers (baseline PTX only)
// ---------------------------------------------------------------------------
__device__ __forceinline__ uint32_t smem_u32(const void* p) {
    uint32_t a;
    asm("{ .reg .u64 t; cvta.to.shared.u64 t, %1; cvt.u32.u64 %0, t; }" : "=r"(a) : "l"(p));
    return a;
}
#define LDM4(r, addr) \
    asm volatile("ldmatrix.sync.aligned.m8n8.x4.shared.b16 {%0,%1,%2,%3}, [%4];" \
        : "=r"((r)[0]), "=r"((r)[1]), "=r"((r)[2]), "=r"((r)[3]) : "r"(addr))
#define MMA_F16(d, a, b0, b1) \
    asm volatile("mma.sync.aligned.m16n8k16.row.col.f32.f16.f16.f32 " \
        "{%0,%1,%2,%3}, {%4,%5,%6,%7}, {%8,%9}, {%0,%1,%2,%3};" \
        : "+f"((d)[0]), "+f"((d)[1]), "+f"((d)[2]), "+f"((d)[3]) \
        : "r"((a)[0]), "r"((a)[1]), "r"((a)[2]), "r"((a)[3]), "r"(b0), "r"(b1))
#define CP16(s, g) \
    asm volatile("cp.async.cg.shared.global [%0], [%1], 16;" \
        :: "r"(s), "l"(__cvta_generic_to_global(g)) : "memory")
#define CP_COMMIT() asm volatile("cp.async.commit_group;" ::: "memory")
#define CP_WAIT1()  asm volatile("cp.async.wait_group 1;" ::: "memory")
#define CP_WAIT0()  asm volatile("cp.async.wait_group 0;" ::: "memory")

__device__ __forceinline__ void split_store2h(__half* dh, __half* dl, float a, float b) {
    __half ha = __float2half(a), hb = __float2half(b);
    *(__half2*)dh = __halves2half2(ha, hb);
    *(__half2*)dl = __floats2half2_rn(a - __half2float(ha), b - __half2float(hb));
}

// ---------------------------------------------------------------------------
// fp32 -> fp16 conversion kernels
// ---------------------------------------------------------------------------
struct alignas(8) h2x2 { __half2 a, b; };

__global__ void cvt_h_kernel(const float* __restrict__ src,
                             __half* __restrict__ hi, int n4)
{
    int i = blockIdx.x * blockDim.x + threadIdx.x;
    if (i >= n4) return;
    float4 v = ((const float4*)src)[i];
    h2x2 hv;
    hv.a = __floats2half2_rn(v.x, v.y);
    hv.b = __floats2half2_rn(v.z, v.w);
    ((h2x2*)hi)[i] = hv;
}

// fused hi/lo split for all 4 weight matrices (grid.y = z)
__global__ void split_h4_kernel(const float* __restrict__ W0, const float* __restrict__ W1,
                                const float* __restrict__ W2, const float* __restrict__ W3,
                                __half* __restrict__ hi, __half* __restrict__ lo, int n4)
{
    int z = blockIdx.y;
    const float* src = (z == 0) ? W0 : (z == 1) ? W1 : (z == 2) ? W2 : W3;
    int i = blockIdx.x * blockDim.x + threadIdx.x;
    if (i >= n4) return;
    size_t o = (size_t)z * n4 + i;
    float4 v = ((const float4*)src)[i];
    __half h0 = __float2half(v.x), h1 = __float2half(v.y);
    __half h2 = __float2half(v.z), h3 = __float2half(v.w);
    h2x2 hv, lv;
    hv.a = __half2(h0, h1); hv.b = __half2(h2, h3);
    lv.a = __floats2half2_rn(v.x - __half2float(h0), v.y - __half2float(h1));
    lv.b = __floats2half2_rn(v.z - __half2float(h2), v.w - __half2float(h3));
    ((h2x2*)hi)[o] = hv;
    ((h2x2*)lo)[o] = lv;
}

// ---------------------------------------------------------------------------
// mma.sync fp16 2-product GEMM tile: C[128,128] = A[128,K] * (Bhi+Blo)[128,K]^T
// (fp32 acc). 8 warps = 2(M) x 4(N); warp tile 64x32; BK=32; 3-stage ring.
// ---------------------------------------------------------------------------
#define TILE_B    10240           // 128 * 40 * 2
#define STAGE_B   (3 * TILE_B)    // 30720
#define GEMM_SMEM (3 * STAGE_B)   // 92160

__device__ __forceinline__ void mma_gemm_tile(
    const __half* __restrict__ Ah,
    const __half* __restrict__ Bh, const __half* __restrict__ Bl,
    uint32_t sbase, float acc[4][4][4])
{
    int tid = threadIdx.x, lane = tid & 31, w = tid >> 5;
    int wm = w & 1, wn = w >> 1;
    uint32_t r8 = lane & 7, mi = lane >> 3;
    uint32_t a_off = ((wm * 64 + ((mi & 1) << 3) + r8) * 40 + ((mi >> 1) << 3)) * 2;
    uint32_t b_off = ((wn * 32 + ((mi >> 1) << 3) + r8) * 40 + ((mi & 1) << 3)) * 2;

    int e0 = tid, e1 = tid + 256;
    int r0 = e0 >> 2, kq0 = e0 & 3;
    int r1 = e1 >> 2, kq1 = e1 & 3;
    uint32_t so0 = (uint32_t)((r0 * 40 + kq0 * 8) * 2);
    uint32_t so1 = (uint32_t)((r1 * 40 + kq1 * 8) * 2);

    auto issue = [&](int c, int buf) {
        uint32_t sb = sbase + buf * STAGE_B;
        size_t gg0 = (size_t)r0 * KDIM + c * 32 + kq0 * 8;
        size_t gg1 = (size_t)r1 * KDIM + c * 32 + kq1 * 8;
        CP16(sb + 0 * TILE_B + so0, Ah + gg0);
        CP16(sb + 0 * TILE_B + so1, Ah + gg1);
        CP16(sb + 1 * TILE_B + so0, Bh + gg0);
        CP16(sb + 1 * TILE_B + so1, Bh + gg1);
        CP16(sb + 2 * TILE_B + so0, Bl + gg0);
        CP16(sb + 2 * TILE_B + so1, Bl + gg1);
    };

    auto compute = [&](int buf) {
        uint32_t sb = sbase + buf * STAGE_B;
#pragma unroll
        for (int ks = 0; ks < 2; ks++) {
            uint32_t k0b = ks * 32;
            uint32_t bh[8], bl[8];
#pragma unroll
            for (int p = 0; p < 2; p++) {
                LDM4(&bh[p * 4], sb + 1 * TILE_B + b_off + p * 1280 + k0b);
                LDM4(&bl[p * 4], sb + 2 * TILE_B + b_off + p * 1280 + k0b);
            }
#pragma unroll
            for (int ma = 0; ma < 4; ma++) {
                uint32_t ah[4];
                LDM4(ah, sb + 0 * TILE_B + a_off + ma * 1280 + k0b);
#pragma unroll
                for (int na = 0; na < 4; na++) {
                    int bi = (na >> 1) * 4 + (na & 1) * 2;
                    MMA_F16(acc[ma][na], ah, bh[bi], bh[bi + 1]);
                    MMA_F16(acc[ma][na], ah, bl[bi], bl[bi + 1]);
                }
            }
        }
    };

    const int NCH = KDIM / 32;   // 64
    issue(0, 0); CP_COMMIT();
    issue(1, 1); CP_COMMIT();
    for (int c = 0; c < NCH; c++) {
        if (c == NCH - 1) { CP_WAIT0(); } else { CP_WAIT1(); }
        __syncthreads();
        if (c + 2 < NCH) { issue(c + 2, (c + 2) % 3); CP_COMMIT(); }
        compute(c % 3);
    }
    __syncthreads();   // protect smem reuse by caller epilogue
}

// ---------------------------------------------------------------------------
// 1-product variant (Wo only): C = A * Bhi^T. 2 tiles/stage, 3-stage ring.
// NOTE: the kernel's dynamic smem must cover the LARGER of the ring (61440 B)
// and the fp32 epilogue staging tile (128*132*4 = 67584 B).
// ---------------------------------------------------------------------------
#define STAGE1_B    (2 * TILE_B)   // 20480
#define GEMM1_RING  (3 * STAGE1_B) // 61440
#define EPI_CS_B    (128 * 132 * 4)// 67584
#define GEMM1_SMEM  EPI_CS_B       // 67584 = max(ring, Cs)

__device__ __forceinline__ void mma_gemm_tile1(
    const __half* __restrict__ Ah, const __half* __restrict__ Bh,
    uint32_t sbase, float acc[4][4][4])
{
    int tid = threadIdx.x, lane = tid & 31, w = tid >> 5;
    int wm = w & 1, wn = w >> 1;
    uint32_t r8 = lane & 7, mi = lane >> 3;
    uint32_t a_off = ((wm * 64 + ((mi & 1) << 3) + r8) * 40 + ((mi >> 1) << 3)) * 2;
    uint32_t b_off = ((wn * 32 + ((mi >> 1) << 3) + r8) * 40 + ((mi & 1) << 3)) * 2;

    int e0 = tid, e1 = tid + 256;
    int r0 = e0 >> 2, kq0 = e0 & 3;
    int r1 = e1 >> 2, kq1 = e1 & 3;
    uint32_t so0 = (uint32_t)((r0 * 40 + kq0 * 8) * 2);
    uint32_t so1 = (uint32_t)((r1 * 40 + kq1 * 8) * 2);

    auto issue = [&](int c, int buf) {
        uint32_t sb = sbase + buf * STAGE1_B;
        size_t gg0 = (size_t)r0 * KDIM + c * 32 + kq0 * 8;
        size_t gg1 = (size_t)r1 * KDIM + c * 32 + kq1 * 8;
        CP16(sb + 0 * TILE_B + so0, Ah + gg0);
        CP16(sb + 0 * TILE_B + so1, Ah + gg1);
        CP16(sb + 1 * TILE_B + so0, Bh + gg0);
        CP16(sb + 1 * TILE_B + so1, Bh + gg1);
    };

    auto compute = [&](int buf) {
        uint32_t sb = sbase + buf * STAGE1_B;
#pragma unroll
        for (int ks = 0; ks < 2; ks++) {
            uint32_t k0b = ks * 32;
            uint32_t bh[8];
#pragma unroll
            for (int p = 0; p < 2; p++)
                LDM4(&bh[p * 4], sb + 1 * TILE_B + b_off + p * 1280 + k0b);
#pragma unroll
            for (int ma = 0; ma < 4; ma++) {
                uint32_t ah[4];
                LDM4(ah, sb + 0 * TILE_B + a_off + ma * 1280 + k0b);
#pragma unroll
                for (int na = 0; na < 4; na++) {
                    int bi = (na >> 1) * 4 + (na & 1) * 2;
                    MMA_F16(acc[ma][na], ah, bh[bi], bh[bi + 1]);
                }
            }
        }
    };

    const int NCH = KDIM / 32;   // 64
    issue(0, 0); CP_COMMIT();
    issue(1, 1); CP_COMMIT();
    for (int c = 0; c < NCH; c++) {
        if (c == NCH - 1) { CP_WAIT0(); } else { CP_WAIT1(); }
        __syncthreads();
        if (c + 2 < NCH) { issue(c + 2, (c + 2) % 3); CP_COMMIT(); }
        compute(c % 3);
    }
    __syncthreads();
}

// stage acc -> smem float[128][132]
__device__ __forceinline__ void acc_to_smem(float* Cs, float acc[4][4][4])
{
    int tid = threadIdx.x, lane = tid & 31, w = tid >> 5;
    int wm = w & 1, wn = w >> 1;
    int g = lane >> 2, tg = lane & 3;
#pragma unroll
    for (int ma = 0; ma < 4; ma++)
#pragma unroll
        for (int na = 0; na < 4; na++) {
            int col = wn * 32 + na * 8 + tg * 2;
            int row = wm * 64 + ma * 16 + g;
            *(float2*)&Cs[row * 132 + col]       = make_float2(acc[ma][na][0], acc[ma][na][1]);
            *(float2*)&Cs[(row + 8) * 132 + col] = make_float2(acc[ma][na][2], acc[ma][na][3]);
        }
}

// ---------------------------------------------------------------------------
// QKV projection: GEMM + RoPE(+scale) + fp16 stores in flash layouts.
// grid (16, 32, 3): n-block = head, m-block = 128 tokens, z = Q/K/V.
// ---------------------------------------------------------------------------
__global__ __launch_bounds__(256, 1)
void qkv_mma_kernel(const __half* __restrict__ xh,
                    const __half* __restrict__ wh, const __half* __restrict__ wl,
                    const float* __restrict__ cosb, const float* __restrict__ sinb)
{
    extern __shared__ char smem[];
    uint32_t sbase = smem_u32(smem);
    int tid = threadIdx.x;
    int z = blockIdx.z;
    int n0 = blockIdx.x * 128, m0 = blockIdx.y * 128;
    int h = n0 >> 7;
    int b = m0 >> 11, t0 = m0 & 2047;
    int bh = b * NHEAD + h;

    const __half* Ah = xh + (size_t)m0 * KDIM;
    const __half* Bh = wh + (size_t)z * HID * KDIM + (size_t)n0 * KDIM;
    const __half* Bl = wl + (size_t)z * HID * KDIM + (size_t)n0 * KDIM;

    float acc[4][4][4];
#pragma unroll
    for (int i = 0; i < 4; i++)
#pragma unroll
        for (int j = 0; j < 4; j++)
#pragma unroll
            for (int c = 0; c < 4; c++) acc[i][j][c] = 0.f;

    mma_gemm_tile(Ah, Bh, Bl, sbase, acc);

    float* Cs = (float*)smem;
    acc_to_smem(Cs, acc);
    __syncthreads();

    if (z < 2) {
        // RoPE (+scale for Q); Q single fp16, K split fp16; store [bh][t][d]
        const float qscale = (z == 0) ? 0.08838834764831845f : 1.0f;
        int r = tid >> 1, half = tid & 1;
        int t = t0 + r;
        int d0 = half * 32;
        size_t rowoff = ((size_t)bh * T_SEQ + t0 + r) * HDIM;
#pragma unroll
        for (int j = 0; j < 32; j += 2) {
            int d = d0 + j;
            float a0 = Cs[r * 132 + d],      a1 = Cs[r * 132 + d + 1];
            float b0 = Cs[r * 132 + d + 64], b1 = Cs[r * 132 + d + 65];
            float c00 = cosb[t * HDIM + d],      s00 = sinb[t * HDIM + d];
            float c01 = cosb[t * HDIM + d + 1],  s01 = sinb[t * HDIM + d + 1];
            float c10 = cosb[t * HDIM + 64 + d],     s10 = sinb[t * HDIM + 64 + d];
            float c11 = cosb[t * HDIM + 64 + d + 1], s11 = sinb[t * HDIM + 64 + d + 1];
            float o00 = (a0 * c00 - b0 * s00) * qscale;
            float o01 = (a1 * c01 - b1 * s01) * qscale;
            float o10 = (b0 * c10 + a0 * s10) * qscale;
            float o11 = (b1 * c11 + a1 * s11) * qscale;
            if (z == 0) {
                *(__half2*)&g_qh16[rowoff + d]      = __floats2half2_rn(o00, o01);
                *(__half2*)&g_qh16[rowoff + 64 + d] = __floats2half2_rn(o10, o11);
            } else {
                split_store2h(&g_kh16[rowoff + d],      &g_kl16[rowoff + d],      o00, o01);
                split_store2h(&g_kh16[rowoff + 64 + d], &g_kl16[rowoff + 64 + d], o10, o11);
            }
        }
    } else {
        // V transpose: store [bh][d][t] split fp16
        __half* dh = g_vth16 + (size_t)bh * HDIM * T_SEQ;
        __half* dl = g_vtl16 + (size_t)bh * HDIM * T_SEQ;
#pragma unroll 4
        for (int i = 0; i < 64; i++) {
            int d = (i & 31) * 4 + (tid >> 6);
            int tl = (i >> 5) * 64 + (tid & 63);
            float val = Cs[tl * 132 + d];
            __half hv = __float2half(val);
            __half lv = __float2half(val - __half2float(hv));
            dh[(size_t)d * T_SEQ + t0 + tl] = hv;
            dl[(size_t)d * T_SEQ + t0 + tl] = lv;
        }
    }
}

// ---------------------------------------------------------------------------
// Flash attention on mma.sync, fp16 2-product, causal. Br=128, Bc=64, D=128.
// 256 threads, 8 warps; warp w owns rows w*16..w*16+15 for the FULL 64 kv cols.
// K/V double-buffered. Q single fp16, K/V split fp16, P single fp16.
// Output fp16 into aoh [m][h*128+d] (= Wo GEMM A layout).
// ---------------------------------------------------------------------------
#define FS_Q      0               // 40960: 4 chunks [128][40] fp16
#define FS_STAGE  40960           // 2 stages x 81920 (KH,KL,VH,VL)
#define FS_P      204800          // 20480: 2 chunks [128][40] fp16
#define FLASH_SMEM 225280

__global__ __launch_bounds__(256, 1)
void flash_hmma_kernel(const __half* __restrict__ qh, const __half* __restrict__ khi,
                       const __half* __restrict__ klo, const __half* __restrict__ vthi,
                       const __half* __restrict__ vtlo, __half* __restrict__ aoh)
{
    extern __shared__ char smem[];
    uint32_t sbase = smem_u32(smem);
    int tid = threadIdx.x, lane = tid & 31, w = tid >> 5;
    int bh = blockIdx.y;
    int qi = gridDim.x - 1 - blockIdx.x;   // heavy tiles first
    int qrow0 = qi * 128;

    const __half* qh_b = qh   + (size_t)bh * T_SEQ * HDIM;
    const __half* kh_b = khi  + (size_t)bh * T_SEQ * HDIM;
    const __half* kl_b = klo  + (size_t)bh * T_SEQ * HDIM;
    const __half* vh_b = vthi + (size_t)bh * HDIM * T_SEQ;
    const __half* vl_b = vtlo + (size_t)bh * HDIM * T_SEQ;

    // Stage Q (128 x 128 fp16) into 4 chunks [128][40]
#pragma unroll
    for (int i = 0; i < 8; i++) {
        int e = tid + i * 256;
        int row = e >> 4, u = e & 15;
        uint32_t sa = sbase + FS_Q + (u >> 2) * 10240 + (row * 40 + (u & 3) * 8) * 2;
        CP16(sa, qh_b + (size_t)(qrow0 + row) * HDIM + u * 8);
    }
    CP_COMMIT();

    auto load_kv = [&](int j, int st) {
        uint32_t sb = sbase + FS_STAGE + st * 81920;
#pragma unroll
        for (int i = 0; i < 4; i++) {
            int e = tid + i * 256;
            int row = e >> 4, u = e & 15;
            uint32_t sa = sb + (u >> 2) * 5120 + (row * 40 + (u & 3) * 8) * 2;
            size_t go = (size_t)(j * 64 + row) * HDIM + u * 8;
            CP16(sa, kh_b + go);
            CP16(sa + 20480, kl_b + go);
        }
#pragma unroll
        for (int i = 0; i < 4; i++) {
            int e = tid + i * 256;
            int d = e >> 3, u = e & 7;
            uint32_t sa = sb + 40960 + (u >> 2) * 10240 + (d * 40 + (u & 3) * 8) * 2;
            size_t go = (size_t)d * T_SEQ + j * 64 + u * 8;
            CP16(sa, vh_b + go);
            CP16(sa + 20480, vl_b + go);
        }
        CP_COMMIT();
    };

    uint32_t r8 = lane & 7, mi = lane >> 3;
    int tg = lane & 3, g = lane >> 2;
    uint32_t aoff = ((w * 16 + (mi & 1) * 8 + r8) * 40 + (mi >> 1) * 8) * 2;
    uint32_t boff = (((mi >> 1) * 8 + r8) * 40 + (mi & 1) * 8) * 2;

    float oacc[16][4];
#pragma unroll
    for (int i = 0; i < 16; i++)
#pragma unroll
        for (int c = 0; c < 4; c++) oacc[i][c] = 0.f;
    float mrow0 = -1e30f, mrow1 = -1e30f, lrow0 = 0.f, lrow1 = 0.f;

    int row0l = w * 16 + g;
    int gr0 = qrow0 + row0l, gr1 = gr0 + 8;
    int jmax = 2 * qi + 1;

    load_kv(0, 0);

    for (int j = 0; j <= jmax; j++) {
        if (j < jmax) { load_kv(j + 1, (j + 1) & 1); CP_WAIT1(); }
        else          { CP_WAIT0(); }
        __syncthreads();
        uint32_t kb = sbase + FS_STAGE + (j & 1) * 81920;
        uint32_t vb = kb + 40960;

        // S = Q K^T (64 cols per warp, 16 rows), 2-product
        float sacc[8][4];
#pragma unroll
        for (int i = 0; i < 8; i++)
#pragma unroll
            for (int c = 0; c < 4; c++) sacc[i][c] = 0.f;

#pragma unroll
        for (int ks = 0; ks < 8; ks++) {
            uint32_t ko = (ks & 1) * 32;
            uint32_t q4[4];
            LDM4(q4, sbase + FS_Q + (ks >> 1) * 10240 + aoff + ko);
#pragma unroll
            for (int nb = 0; nb < 4; nb++) {
                uint32_t kh4[4], kl4[4];
                LDM4(kh4, kb + (ks >> 1) * 5120 + boff + nb * 1280 + ko);
                LDM4(kl4, kb + 20480 + (ks >> 1) * 5120 + boff + nb * 1280 + ko);
                MMA_F16(sacc[nb * 2],     q4, kh4[0], kh4[1]);
                MMA_F16(sacc[nb * 2],     q4, kl4[0], kl4[1]);
                MMA_F16(sacc[nb * 2 + 1], q4, kh4[2], kh4[3]);
                MMA_F16(sacc[nb * 2 + 1], q4, kl4[2], kl4[3]);
            }
        }

        // causal mask (only the two diagonal tiles need it)
        if (j >= 2 * qi) {
#pragma unroll
            for (int na = 0; na < 8; na++) {
                int gc = j * 64 + na * 8 + tg * 2;
                if (gc     > gr0) sacc[na][0] = -1e30f;
                if (gc + 1 > gr0) sacc[na][1] = -1e30f;
                if (gc     > gr1) sacc[na][2] = -1e30f;
                if (gc + 1 > gr1) sacc[na][3] = -1e30f;
            }
        }

        // online softmax (rows gr0, gr1); reduce over 4-lane tg group
        float m0 = -1e30f, m1 = -1e30f;
#pragma unroll
        for (int na = 0; na < 8; na++) {
            m0 = fmaxf(m0, fmaxf(sacc[na][0], sacc[na][1]));
            m1 = fmaxf(m1, fmaxf(sacc[na][2], sacc[na][3]));
        }
        m0 = fmaxf(m0, __shfl_xor_sync(0xffffffffu, m0, 1));
        m0 = fmaxf(m0, __shfl_xor_sync(0xffffffffu, m0, 2));
        m1 = fmaxf(m1, __shfl_xor_sync(0xffffffffu, m1, 1));
        m1 = fmaxf(m1, __shfl_xor_sync(0xffffffffu, m1, 2));
        float mn0 = fmaxf(mrow0, m0), mn1 = fmaxf(mrow1, m1);
        float cr0 = __expf(mrow0 - mn0), cr1 = __expf(mrow1 - mn1);
        float s0 = 0.f, s1 = 0.f;
#pragma unroll
        for (int na = 0; na < 8; na++) {
            float p00 = __expf(sacc[na][0] - mn0);
            float p01 = __expf(sacc[na][1] - mn0);
            float p10 = __expf(sacc[na][2] - mn1);
            float p11 = __expf(sacc[na][3] - mn1);
            s0 += p00 + p01; s1 += p10 + p11;
            // P single fp16 store (chunked [128][40], warp-private rows)
            char* basep = smem + FS_P + (na >> 2) * 10240;
            uint32_t cw = (na & 3) * 8 + tg * 2;
            *(__half2*)(basep + (row0l * 40 + cw) * 2)       = __floats2half2_rn(p00, p01);
            *(__half2*)(basep + ((row0l + 8) * 40 + cw) * 2) = __floats2half2_rn(p10, p11);
        }
        s0 += __shfl_xor_sync(0xffffffffu, s0, 1);
        s0 += __shfl_xor_sync(0xffffffffu, s0, 2);
        s1 += __shfl_xor_sync(0xffffffffu, s1, 1);
        s1 += __shfl_xor_sync(0xffffffffu, s1, 2);
        lrow0 = lrow0 * cr0 + s0;  lrow1 = lrow1 * cr1 + s1;
        mrow0 = mn0;               mrow1 = mn1;
#pragma unroll
        for (int na = 0; na < 16; na++) {
            oacc[na][0] *= cr0; oacc[na][1] *= cr0;
            oacc[na][2] *= cr1; oacc[na][3] *= cr1;
        }
        __syncwarp();

        // O += P V  (A = P rows of this warp; B = V^T, n = d 128), 2-product
#pragma unroll
        for (int kvs = 0; kvs < 4; kvs++) {
            uint32_t ko = (kvs & 1) * 32;
            uint32_t p4[4];
            LDM4(p4, sbase + FS_P + (kvs >> 1) * 10240 + aoff + ko);
#pragma unroll
            for (int nb = 0; nb < 8; nb++) {
                uint32_t vh4[4], vl4[4];
                LDM4(vh4, vb + (kvs >> 1) * 10240 + boff + nb * 1280 + ko);
                LDM4(vl4, vb + 20480 + (kvs >> 1) * 10240 + boff + nb * 1280 + ko);
                MMA_F16(oacc[nb * 2],     p4, vh4[0], vh4[1]);
                MMA_F16(oacc[nb * 2],     p4, vl4[0], vl4[1]);
                MMA_F16(oacc[nb * 2 + 1], p4, vh4[2], vh4[3]);
                MMA_F16(oacc[nb * 2 + 1], p4, vl4[2], vl4[3]);
            }
        }
        __syncthreads();   // all warps done with this stage before overwrite at j+2
    }

    // epilogue: normalize, convert fp16, store into Wo's A layout [m][h*128+d]
    int bb = bh >> 4, hh = bh & 15;
    float inv0 = 1.f / lrow0, inv1 = 1.f / lrow1;
    size_t m0i = (size_t)(bb * T_SEQ + gr0) * HID + hh * HDIM;
    size_t m1i = (size_t)(bb * T_SEQ + gr1) * HID + hh * HDIM;
#pragma unroll
    for (int na = 0; na < 16; na++) {
        int col = na * 8 + tg * 2;
        *(__half2*)&aoh[m0i + col] = __floats2half2_rn(oacc[na][0] * inv0, oacc[na][1] * inv0);
        *(__half2*)&aoh[m1i + col] = __floats2half2_rn(oacc[na][2] * inv1, oacc[na][3] * inv1);
    }
}

// ---------------------------------------------------------------------------
// Output projection on mma.sync (1-product): out[m, n] row-major fp32.
// ---------------------------------------------------------------------------
__global__ __launch_bounds__(256, 1)
void wo_mma_kernel(const __half* __restrict__ ah,
                   const __half* __restrict__ wh,
                   float* __restrict__ out)
{
    extern __shared__ char smem[];
    uint32_t sbase = smem_u32(smem);
    int tid = threadIdx.x;
    int n0 = blockIdx.x * 128, m0 = blockIdx.y * 128;

    const __half* Ah = ah + (size_t)m0 * KDIM;
    const __half* Bh = wh + (size_t)3 * HID * KDIM + (size_t)n0 * KDIM;

    float acc[4][4][4];
#pragma unroll
    for (int i = 0; i < 4; i++)
#pragma unroll
        for (int j = 0; j < 4; j++)
#pragma unroll
            for (int c = 0; c < 4; c++) acc[i][j][c] = 0.f;

    mma_gemm_tile1(Ah, Bh, sbase, acc);

    float* Cs = (float*)smem;
    acc_to_smem(Cs, acc);
    __syncthreads();

    int r = tid >> 1, half = tid & 1;
    float* outp = out + (size_t)(m0 + r) * HID + n0 + half * 64;
#pragma unroll
    for (int j = 0; j < 64; j += 4)
        *(float4*)&outp[j] = *(float4*)&Cs[r * 132 + half * 64 + j];
}

// ---------------------------------------------------------------------------
extern "C" void kernel_launch(void* const* d_in, const int* in_sizes, int n_in,
                              void* d_out, int out_size)
{
    const float* x    = (const float*)d_in[0];
    const float* cosb = (const float*)d_in[1];
    const float* sinb = (const float*)d_in[2];
    const float* Wq   = (const float*)d_in[3];
    const float* Wk   = (const float*)d_in[4];
    const float* Wv   = (const float*)d_in[5];
    const float* Wo   = (const float*)d_in[6];
    float* out = (float*)d_out;

    __half *xh, *wh, *wl, *qh, *kh, *kl, *vth, *vtl;
    cudaGetSymbolAddress((void**)&xh,  g_xh);
    cudaGetSymbolAddress((void**)&wh,  g_wh);
    cudaGetSymbolAddress((void**)&wl,  g_wl);
    cudaGetSymbolAddress((void**)&qh,  g_qh16);
    cudaGetSymbolAddress((void**)&kh,  g_kh16);
    cudaGetSymbolAddress((void**)&kl,  g_kl16);
    cudaGetSymbolAddress((void**)&vth, g_vth16);
    cudaGetSymbolAddress((void**)&vtl, g_vtl16);

    // 1) x -> fp16; weights -> fp16 hi/lo split (one fused launch)
    const int XN4 = MROWS * KDIM / 4;
    const int WN4 = HID * KDIM / 4;
    cvt_h_kernel<<<XN4 / 256, 256>>>(x, xh, XN4);
    split_h4_kernel<<<dim3(WN4 / 256, 4), 256>>>(Wq, Wk, Wv, Wo, wh, wl, WN4);

    // 2) QKV projection + RoPE + layout fusion (fp16 flash buffers)
    cudaFuncSetAttribute(qkv_mma_kernel, cudaFuncAttributeMaxDynamicSharedMemorySize, GEMM_SMEM);
    qkv_mma_kernel<<<dim3(HID / 128, MROWS / 128, 3), 256, GEMM_SMEM>>>(
        xh, wh, wl, cosb, sinb);

    // 3) flash attention (fp16 2-product, double-buffered K/V); out -> g_xh
    cudaFuncSetAttribute(flash_hmma_kernel, cudaFuncAttributeMaxDynamicSharedMemorySize, FLASH_SMEM);
    flash_hmma_kernel<<<dim3(T_SEQ / 128, BATCH * NHEAD), 256, FLASH_SMEM>>>(
        qh, kh, kl, vth, vtl, xh);

    // 4) output projection (fp16 1-product); smem covers ring AND fp32 epilogue tile
    cudaFuncSetAttribute(wo_mma_kernel, cudaFuncAttributeMaxDynamicSharedMemorySize, GEMM1_SMEM);
    wo_mma_kernel<<<dim3(HID / 128, MROWS / 128), 256, GEMM1_SMEM>>>(xh, wh, out);
}